// round 1
// baseline (speedup 1.0000x reference)
#include <cuda_runtime.h>
#include <math.h>

#define Bb   16
#define Nn   256
#define Ff   128
#define Hh   8
#define DHh  16
#define Ll   9
#define BNn  4096
#define Emax 65536

// ---------------- scratch (device globals; no allocations) ----------------
__device__ float g_m[Bb*Nn*Nn];
__device__ float g_r[Bb*Nn*Nn];
__device__ float g_t[Bb*Nn*Nn];
__device__ float g_deg[BNn];
__device__ float g_enorm[Emax];
__device__ float g_out[BNn*Ff];
__device__ float g_h[BNn*Ff];
__device__ float g_agg[BNn*Ff];
__device__ float g_q[BNn*Ff];
__device__ float g_k[BNn*Ff];
__device__ float g_v[BNn*Ff];
__device__ float g_o[BNn*Ff];
__device__ float g_x[BNn*Ff];
__device__ float g_f1[BNn*2*Ff];

__device__ __forceinline__ float warpsum(float v){
#pragma unroll
    for(int o=16;o;o>>=1) v += __shfl_xor_sync(0xffffffffu, v, o);
    return v;
}

__device__ __forceinline__ float gelu_exact(float x){
    return 0.5f*x*(1.0f + erff(x*0.70710678118654752f));
}

// ---------------- simple utility kernels ----------------
__global__ void k_zero(float* __restrict__ p, int n){
    int i = blockIdx.x*blockDim.x + threadIdx.x;
    if(i<n) p[i]=0.f;
}

__global__ void k_build_adj(const int* __restrict__ ei, int E){
    int e = blockIdx.x*blockDim.x + threadIdx.x;
    if(e>=E) return;
    int row = ei[e], col = ei[E+e];
    int eb = row/Nn, es = row%Nn, et = col%Nn;
    g_m[(eb*Nn+es)*Nn + et] = 1.0f;
}

__global__ void k_selfloop(const int* __restrict__ n_counts){
    int i = blockIdx.x*blockDim.x + threadIdx.x;
    if(i>=BNn) return;
    int b = i/Nn, n = i%Nn;
    if(n < n_counts[b]) g_m[(b*Nn+n)*Nn + n] = 1.0f;
}

// per-row normalize (optionally x^6 first).  grid = B*N rows, block = 256
__global__ void k_rownorm(const float* __restrict__ src, float* __restrict__ dst, int pow6){
    int row = blockIdx.x;
    int t   = threadIdx.x;
    float v = src[row*Nn + t];
    if(pow6){ float v2=v*v; v = v2*v2*v2; }
    float s = warpsum(v);
    __shared__ float ws[8];
    __shared__ float tot_s;
    if((t&31)==0) ws[t>>5] = s;
    __syncthreads();
    if(t==0){
        float tot=0;
#pragma unroll
        for(int i=0;i<8;i++) tot += ws[i];
        tot_s = tot;
    }
    __syncthreads();
    dst[row*Nn + t] = v / (tot_s + 1e-6f);
}

// ---------------- batched NxN @ NxN (MCL):  C[b] = A[b] @ B[b] ----------------
// 64x64 tile, 256 threads, 4x4 micro-tile, BK=16, K-major smem tiles.
__global__ void k_bmm(const float* __restrict__ A, const float* __restrict__ B, float* __restrict__ C){
    int b = blockIdx.z;
    const float* Ab = A + (size_t)b*Nn*Nn;
    const float* Bp = B + (size_t)b*Nn*Nn;
    float*       Cb = C + (size_t)b*Nn*Nn;

    __shared__ float As[16][68];
    __shared__ float Bs[16][68];
    int tid = threadIdx.x;
    int tx = tid & 15, ty = tid >> 4;
    int row0 = blockIdx.y*64, col0 = blockIdx.x*64;
    float acc[4][4] = {};

    int lr = tid>>2, lk = (tid&3)*4;       // A transpose-load indices
    int bk = tid>>4, bc = (tid&15)*4;      // B direct-load indices

    for(int k0=0;k0<Nn;k0+=16){
        float4 a4 = *(const float4*)(Ab + (size_t)(row0+lr)*Nn + k0+lk);
        As[lk  ][lr]=a4.x; As[lk+1][lr]=a4.y; As[lk+2][lr]=a4.z; As[lk+3][lr]=a4.w;
        float4 b4 = *(const float4*)(Bp + (size_t)(k0+bk)*Nn + col0+bc);
        *(float4*)&Bs[bk][bc] = b4;
        __syncthreads();
#pragma unroll
        for(int k=0;k<16;k++){
            float4 av = *(const float4*)&As[k][ty*4];
            float4 wv = *(const float4*)&Bs[k][tx*4];
            float aa[4]={av.x,av.y,av.z,av.w};
            float ww[4]={wv.x,wv.y,wv.z,wv.w};
#pragma unroll
            for(int i=0;i<4;i++)
#pragma unroll
                for(int j=0;j<4;j++) acc[i][j] += aa[i]*ww[j];
        }
        __syncthreads();
    }
#pragma unroll
    for(int i=0;i<4;i++){
        int r = row0 + ty*4 + i;
#pragma unroll
        for(int j=0;j<4;j++) Cb[(size_t)r*Nn + col0 + tx*4 + j] = acc[i][j];
    }
}

// ---------------- generic GEMM: C[M,Nc] = act(alpha * A[M,K] @ W[Nc,K]^T + bias) ----------------
// ACT: 0 = none, 1 = exact gelu
template<int ACT>
__global__ void k_gemm(const float* __restrict__ A, const float* __restrict__ W,
                       const float* __restrict__ bias, float* __restrict__ C,
                       int M, int Nc, int K, float alpha){
    __shared__ float As[16][68];
    __shared__ float Ws[16][68];
    int tid = threadIdx.x;
    int tx = tid & 15, ty = tid >> 4;
    int row0 = blockIdx.y*64, col0 = blockIdx.x*64;
    float acc[4][4] = {};
    int lr = tid>>2, lk = (tid&3)*4;

    for(int k0=0;k0<K;k0+=16){
        float4 a4 = *(const float4*)(A + (size_t)(row0+lr)*K + k0+lk);
        As[lk  ][lr]=a4.x; As[lk+1][lr]=a4.y; As[lk+2][lr]=a4.z; As[lk+3][lr]=a4.w;
        float4 w4 = *(const float4*)(W + (size_t)(col0+lr)*K + k0+lk);
        Ws[lk  ][lr]=w4.x; Ws[lk+1][lr]=w4.y; Ws[lk+2][lr]=w4.z; Ws[lk+3][lr]=w4.w;
        __syncthreads();
#pragma unroll
        for(int k=0;k<16;k++){
            float4 av = *(const float4*)&As[k][ty*4];
            float4 wv = *(const float4*)&Ws[k][tx*4];
            float aa[4]={av.x,av.y,av.z,av.w};
            float ww[4]={wv.x,wv.y,wv.z,wv.w};
#pragma unroll
            for(int i=0;i<4;i++)
#pragma unroll
                for(int j=0;j<4;j++) acc[i][j] += aa[i]*ww[j];
        }
        __syncthreads();
    }
#pragma unroll
    for(int i=0;i<4;i++){
        int r = row0 + ty*4 + i;
#pragma unroll
        for(int j=0;j<4;j++){
            int c = col0 + tx*4 + j;
            float v = acc[i][j]*alpha;
            if(bias) v += bias[c];
            if(ACT==1) v = gelu_exact(v);
            C[(size_t)r*Nc + c] = v;
        }
    }
}

// ---------------- degree & edge norm ----------------
__global__ void k_deg(const int* __restrict__ ei, int E){
    int e = blockIdx.x*blockDim.x + threadIdx.x;
    if(e<E) atomicAdd(&g_deg[ei[e]], 1.0f);
}
__global__ void k_enorm(const int* __restrict__ ei, int E){
    int e = blockIdx.x*blockDim.x + threadIdx.x;
    if(e>=E) return;
    float dr = g_deg[ei[e]]   + 1.0f;
    float dc = g_deg[ei[E+e]] + 1.0f;
    g_enorm[e] = rsqrtf(dr)*rsqrtf(dc);
}

// ---------------- GCN edge messages: msg = enorm*relu(h[row]+edge_attr@ew^T); atomic into agg[col] ----------------
__global__ void k_edge_msg(const int* __restrict__ ei, int E,
                           const float* __restrict__ eattr, const float* __restrict__ ew){
    int idx = blockIdx.x*blockDim.x + threadIdx.x;
    int e = idx >> 5;
    if(e>=E) return;
    int j = idx & 31;
    int row = ei[e], col = ei[E+e];
    float en = g_enorm[e];
    float ea0=eattr[e*7+0], ea1=eattr[e*7+1], ea2=eattr[e*7+2], ea3=eattr[e*7+3],
          ea4=eattr[e*7+4], ea5=eattr[e*7+5], ea6=eattr[e*7+6];
#pragma unroll
    for(int c=0;c<4;c++){
        int f = j + 32*c;
        const float* w = ew + f*7;
        float s = g_h[(size_t)row*Ff + f]
                + ea0*w[0]+ea1*w[1]+ea2*w[2]+ea3*w[3]+ea4*w[4]+ea5*w[5]+ea6*w[6];
        s = fmaxf(s, 0.f) * en;
        atomicAdd(&g_agg[(size_t)col*Ff + f], s);
    }
}

// ---------------- GCN node update (fused): out += relu(LN(agg + relu(h+emb[root])/deg)) ----------------
__global__ void k_node(const float* __restrict__ gg, const float* __restrict__ gb,
                       const float* __restrict__ emb, const int* __restrict__ root){
    int warp = threadIdx.x>>5, lane = threadIdx.x&31;
    int n = blockIdx.x*8 + warp;
    float dvinv = 1.0f / (g_deg[n] + 1.0f);
    const float* er = emb + root[n]*Ff;
    float t[4]; float s=0;
#pragma unroll
    for(int c=0;c<4;c++){
        int f = c*32 + lane;
        float hv = g_h[(size_t)n*Ff+f] + er[f];
        t[c] = g_agg[(size_t)n*Ff+f] + fmaxf(hv,0.f)*dvinv;
        s += t[c];
    }
    float mean = warpsum(s) * (1.f/Ff);
    float vv=0;
#pragma unroll
    for(int c=0;c<4;c++){ float d=t[c]-mean; vv += d*d; }
    float inv = rsqrtf(warpsum(vv)*(1.f/Ff) + 1e-5f);
#pragma unroll
    for(int c=0;c<4;c++){
        int f = c*32 + lane;
        float y = (t[c]-mean)*inv*gg[f] + gb[f];
        g_out[(size_t)n*Ff+f] += fmaxf(y, 0.f);
    }
}

// ---------------- residual + layernorm: out = LN(a [+ res]) * g + b ----------------
__global__ void k_addln(const float* __restrict__ a, const float* __restrict__ res,
                        const float* __restrict__ gg, const float* __restrict__ gb,
                        float* __restrict__ out){
    int warp = threadIdx.x>>5, lane = threadIdx.x&31;
    int n = blockIdx.x*8 + warp;
    float t[4]; float s=0;
#pragma unroll
    for(int c=0;c<4;c++){
        int f = c*32 + lane;
        float v = a[(size_t)n*Ff+f];
        if(res) v += res[(size_t)n*Ff+f];
        t[c]=v; s+=v;
    }
    float mean = warpsum(s) * (1.f/Ff);
    float vv=0;
#pragma unroll
    for(int c=0;c<4;c++){ float d=t[c]-mean; vv += d*d; }
    float inv = rsqrtf(warpsum(vv)*(1.f/Ff) + 1e-5f);
#pragma unroll
    for(int c=0;c<4;c++){
        int f = c*32 + lane;
        out[(size_t)n*Ff+f] = (t[c]-mean)*inv*gg[f] + gb[f];
    }
}

// ---------------- fused attention: one thread per (b,h,row), K/V in SMEM, online softmax ----------------
// grid (H, B), block 256.  q already scaled by dh^-0.5.
__global__ void k_attn(const float* __restrict__ mclw, const int* __restrict__ n_counts){
    int h = blockIdx.x, b = blockIdx.y;
    __shared__ float ks[Nn][DHh];
    __shared__ float vs[Nn][DHh];
    int tid = threadIdx.x;

    // load K/V slices for this (b,h)
#pragma unroll
    for(int c=0;c<4;c++){
        *(float4*)&ks[tid][c*4] = *(const float4*)(g_k + ((size_t)(b*Nn+tid)*Ff) + h*DHh + c*4);
        *(float4*)&vs[tid][c*4] = *(const float4*)(g_v + ((size_t)(b*Nn+tid)*Ff) + h*DHh + c*4);
    }
    __syncthreads();

    int n  = tid;
    int nc = n_counts[b];
    bool vn = (n < nc);
    float w = mclw[h];
    const float* mrow = g_r + ((size_t)(b*Nn+n))*Nn;

    float qr[DHh];
#pragma unroll
    for(int d=0;d<DHh;d++) qr[d] = g_q[((size_t)(b*Nn+n))*Ff + h*DHh + d];

    float mx = -1e30f, sum = 0.f, acc[DHh] = {};
    for(int m=0;m<Nn;m++){
        float s = 0.f;
#pragma unroll
        for(int d=0;d<DHh;d++) s += qr[d]*ks[m][d];
        float bias = ((vn && (m<nc)) ? 0.f : -1024.f) + mrow[m]*w;
        s += bias;
        if(s > mx){
            float sc = __expf(mx - s);
            sum *= sc;
#pragma unroll
            for(int d=0;d<DHh;d++) acc[d] *= sc;
            mx = s;
        }
        float p = __expf(s - mx);
        sum += p;
#pragma unroll
        for(int d=0;d<DHh;d++) acc[d] += p*vs[m][d];
    }
    float inv = 1.f/sum;
#pragma unroll
    for(int d=0;d<DHh;d++) g_o[((size_t)(b*Nn+n))*Ff + h*DHh + d] = acc[d]*inv;
}

// ---------------- host ----------------
extern "C" void kernel_launch(void* const* d_in, const int* in_sizes, int n_in,
                              void* d_out, int out_size){
    (void)n_in; (void)out_size;
    const float* input_x      = (const float*)d_in[0];
    const float* edge_attr    = (const float*)d_in[1];
    const float* gcn_lin_w    = (const float*)d_in[2];
    const float* gcn_root_emb = (const float*)d_in[3];
    const float* gcn_edge_w   = (const float*)d_in[4];
    const float* gcn_norm_g   = (const float*)d_in[5];
    const float* gcn_norm_b   = (const float*)d_in[6];
    const float* ln_in_g      = (const float*)d_in[7];
    const float* ln_in_b      = (const float*)d_in[8];
    const float* ln_ffn_g     = (const float*)d_in[9];
    const float* ln_ffn_b     = (const float*)d_in[10];
    const float* mcl_w        = (const float*)d_in[11];
    const float* q_w          = (const float*)d_in[12];
    const float* k_w          = (const float*)d_in[13];
    const float* v_w          = (const float*)d_in[14];
    const float* merge_w      = (const float*)d_in[15];
    const float* merge_b      = (const float*)d_in[16];
    const float* ffn_w1       = (const float*)d_in[17];
    const float* ffn_b1       = (const float*)d_in[18];
    const float* ffn_w2       = (const float*)d_in[19];
    const float* ffn_b2       = (const float*)d_in[20];
    const float* final_g      = (const float*)d_in[21];
    const float* final_b      = (const float*)d_in[22];
    const int*   edge_index   = (const int*)d_in[23];
    const int*   n_counts     = (const int*)d_in[24];
    const int*   root         = (const int*)d_in[25];
    int E = in_sizes[23] / 2;

    float *m_p,*r_p,*t_p,*deg_p,*out_p,*h_p,*agg_p,*q_p,*k_p,*v_p,*o_p,*x_p,*f1_p;
    cudaGetSymbolAddress((void**)&m_p,   g_m);
    cudaGetSymbolAddress((void**)&r_p,   g_r);
    cudaGetSymbolAddress((void**)&t_p,   g_t);
    cudaGetSymbolAddress((void**)&deg_p, g_deg);
    cudaGetSymbolAddress((void**)&out_p, g_out);
    cudaGetSymbolAddress((void**)&h_p,   g_h);
    cudaGetSymbolAddress((void**)&agg_p, g_agg);
    cudaGetSymbolAddress((void**)&q_p,   g_q);
    cudaGetSymbolAddress((void**)&k_p,   g_k);
    cudaGetSymbolAddress((void**)&v_p,   g_v);
    cudaGetSymbolAddress((void**)&o_p,   g_o);
    cudaGetSymbolAddress((void**)&x_p,   g_x);
    cudaGetSymbolAddress((void**)&f1_p,  g_f1);

    // ---- adjacency + MCL ----
    k_zero<<<(Bb*Nn*Nn+255)/256,256>>>(m_p, Bb*Nn*Nn);
    k_build_adj<<<(E+255)/256,256>>>(edge_index, E);
    k_selfloop<<<(BNn+255)/256,256>>>(n_counts);
    k_rownorm<<<Bb*Nn,256>>>(m_p, m_p, 0);              // m
    const float* rcur = m_p;
    for(int i=0;i<6;i++){
        k_bmm<<<dim3(4,4,Bb),256>>>(m_p, rcur, t_p);    // t = m @ r
        k_rownorm<<<Bb*Nn,256>>>(t_p, r_p, ((i+1)%3==0)?1:0);
        rcur = r_p;
    }
    // mcl lives in g_r

    // ---- degree / edge norm ----
    k_zero<<<(BNn+255)/256,256>>>(deg_p, BNn);
    k_deg<<<(E+255)/256,256>>>(edge_index, E);
    k_enorm<<<(E+255)/256,256>>>(edge_index, E);

    // ---- out = input ----
    cudaMemcpyAsync(out_p, input_x, (size_t)BNn*Ff*sizeof(float), cudaMemcpyDeviceToDevice, 0);

    dim3 g128(Ff/64, BNn/64);        // (2,64)
    dim3 g256(2*Ff/64, BNn/64);      // (4,64)

    for(int l=0;l<Ll;l++){
        // ---- GCN ----
        k_gemm<0><<<g128,256>>>(out_p, gcn_lin_w + (size_t)l*Ff*Ff, nullptr, h_p, BNn, Ff, Ff, 1.f);
        k_zero<<<(BNn*Ff+255)/256,256>>>(agg_p, BNn*Ff);
        k_edge_msg<<<(E*32+255)/256,256>>>(edge_index, E, edge_attr, gcn_edge_w + (size_t)l*Ff*7);
        k_node<<<BNn/8,256>>>(gcn_norm_g + l*Ff, gcn_norm_b + l*Ff,
                              gcn_root_emb + (size_t)l*2*Ff, root);

        // ---- attention ----
        k_gemm<0><<<g128,256>>>(out_p, q_w + (size_t)l*Ff*Ff, nullptr, q_p, BNn, Ff, Ff, 0.25f);
        k_gemm<0><<<g128,256>>>(out_p, k_w + (size_t)l*Ff*Ff, nullptr, k_p, BNn, Ff, Ff, 1.f);
        k_gemm<0><<<g128,256>>>(out_p, v_w + (size_t)l*Ff*Ff, nullptr, v_p, BNn, Ff, Ff, 1.f);
        k_attn<<<dim3(Hh,Bb),256>>>(mcl_w + l*Hh, n_counts);
        k_gemm<0><<<g128,256>>>(o_p, merge_w + (size_t)l*Ff*Ff, merge_b + l*Ff, h_p, BNn, Ff, Ff, 1.f);
        k_addln<<<BNn/8,256>>>(h_p, out_p, ln_in_g + l*Ff, ln_in_b + l*Ff, x_p);

        // ---- FFN ----
        k_gemm<1><<<g256,256>>>(x_p, ffn_w1 + (size_t)l*2*Ff*Ff, ffn_b1 + (size_t)l*2*Ff,
                                f1_p, BNn, 2*Ff, Ff, 1.f);
        k_gemm<0><<<g128,256>>>(f1_p, ffn_w2 + (size_t)l*Ff*2*Ff, ffn_b2 + l*Ff,
                                h_p, BNn, Ff, 2*Ff, 1.f);
        k_addln<<<BNn/8,256>>>(x_p, h_p, ln_ffn_g + l*Ff, ln_ffn_b + l*Ff, out_p);
    }

    // ---- final layernorm ----
    k_addln<<<BNn/8,256>>>(out_p, nullptr, final_g, final_b, (float*)d_out);
}

// round 2
// speedup vs baseline: 1.3167x; 1.3167x over previous
#include <cuda_runtime.h>
#include <math.h>

#define Bb   16
#define Nn   256
#define Ff   128
#define Hh   8
#define DHh  16
#define Ll   9
#define BNn  4096
#define Emax 65536

// ---------------- scratch (device globals; no allocations) ----------------
__device__ float g_m[Bb*Nn*Nn];
__device__ float g_r[Bb*Nn*Nn];
__device__ float g_t[Bb*Nn*Nn];
__device__ float g_deg[BNn];
__device__ float g_enorm[Emax];
__device__ float g_out[BNn*Ff];
__device__ float g_h[BNn*Ff];
__device__ float g_q[BNn*Ff];
__device__ float g_k[BNn*Ff];
__device__ float g_v[BNn*Ff];
__device__ float g_o[BNn*Ff];
__device__ float g_x[BNn*Ff];
__device__ float g_f1[BNn*2*Ff];
// CSR by col
__device__ int g_cnt[BNn];
__device__ int g_off[BNn+1];
__device__ int g_cur[BNn];
__device__ int g_elist[Emax];

__device__ __forceinline__ float warpsum(float v){
#pragma unroll
    for(int o=16;o;o>>=1) v += __shfl_xor_sync(0xffffffffu, v, o);
    return v;
}

__device__ __forceinline__ float gelu_exact(float x){
    return 0.5f*x*(1.0f + erff(x*0.70710678118654752f));
}

// ---------------- simple utility kernels ----------------
__global__ void k_zero(float* __restrict__ p, int n){
    int i = blockIdx.x*blockDim.x + threadIdx.x;
    if(i<n) p[i]=0.f;
}
__global__ void k_zeroi(int* __restrict__ p, int n){
    int i = blockIdx.x*blockDim.x + threadIdx.x;
    if(i<n) p[i]=0;
}

__global__ void k_build_adj(const int* __restrict__ ei, int E){
    int e = blockIdx.x*blockDim.x + threadIdx.x;
    if(e>=E) return;
    int row = ei[e], col = ei[E+e];
    int eb = row/Nn, es = row%Nn, et = col%Nn;
    g_m[(eb*Nn+es)*Nn + et] = 1.0f;
}

__global__ void k_selfloop(const int* __restrict__ n_counts){
    int i = blockIdx.x*blockDim.x + threadIdx.x;
    if(i>=BNn) return;
    int b = i/Nn, n = i%Nn;
    if(n < n_counts[b]) g_m[(b*Nn+n)*Nn + n] = 1.0f;
}

// per-row normalize (optionally x^6 first).  4 rows/block, float4.
__global__ void k_rownorm(const float* __restrict__ src, float* __restrict__ dst, int pow6){
    int tid = threadIdx.x;
    int rloc = tid >> 6;             // 0..3
    int sub  = tid & 63;             // 64 threads per row, float4 each
    int row  = blockIdx.x*4 + rloc;
    float4 v = *(const float4*)(src + (size_t)row*Nn + sub*4);
    if(pow6){
        float a2;
        a2=v.x*v.x; v.x=a2*a2*a2;
        a2=v.y*v.y; v.y=a2*a2*a2;
        a2=v.z*v.z; v.z=a2*a2*a2;
        a2=v.w*v.w; v.w=a2*a2*a2;
    }
    float s = v.x+v.y+v.z+v.w;
    s = warpsum(s);                  // per-warp sum = half-row
    __shared__ float hs[8];
    if((tid&31)==0) hs[tid>>5] = s;
    __syncthreads();
    float tot = hs[rloc*2] + hs[rloc*2+1];
    float inv = 1.0f/(tot + 1e-6f);
    v.x*=inv; v.y*=inv; v.z*=inv; v.w*=inv;
    *(float4*)(dst + (size_t)row*Nn + sub*4) = v;
}

// ---------------- batched NxN @ NxN (MCL), double-buffered ----------------
__global__ void __launch_bounds__(256) k_bmm(const float* __restrict__ A, const float* __restrict__ B, float* __restrict__ C){
    int b = blockIdx.z;
    const float* Ab = A + (size_t)b*Nn*Nn;
    const float* Bp = B + (size_t)b*Nn*Nn;
    float*       Cb = C + (size_t)b*Nn*Nn;

    __shared__ float As[16][68];
    __shared__ float Bs[16][68];
    int tid = threadIdx.x;
    int tx = tid & 15, ty = tid >> 4;
    int row0 = blockIdx.y*64, col0 = blockIdx.x*64;
    float acc[4][4] = {};

    int lr = tid>>2, lk = (tid&3)*4;
    int bk = tid>>4, bc = (tid&15)*4;

    float4 pa = *(const float4*)(Ab + (size_t)(row0+lr)*Nn + lk);
    float4 pb = *(const float4*)(Bp + (size_t)bk*Nn + col0+bc);

    for(int k0=0;k0<Nn;k0+=16){
        As[lk  ][lr]=pa.x; As[lk+1][lr]=pa.y; As[lk+2][lr]=pa.z; As[lk+3][lr]=pa.w;
        *(float4*)&Bs[bk][bc] = pb;
        __syncthreads();
        if(k0+16<Nn){
            pa = *(const float4*)(Ab + (size_t)(row0+lr)*Nn + k0+16+lk);
            pb = *(const float4*)(Bp + (size_t)(k0+16+bk)*Nn + col0+bc);
        }
#pragma unroll
        for(int k=0;k<16;k++){
            float4 av = *(const float4*)&As[k][ty*4];
            float4 wv = *(const float4*)&Bs[k][tx*4];
            float aa[4]={av.x,av.y,av.z,av.w};
            float ww[4]={wv.x,wv.y,wv.z,wv.w};
#pragma unroll
            for(int i=0;i<4;i++)
#pragma unroll
                for(int j=0;j<4;j++) acc[i][j] += aa[i]*ww[j];
        }
        __syncthreads();
    }
#pragma unroll
    for(int i=0;i<4;i++){
        int r = row0 + ty*4 + i;
#pragma unroll
        for(int j=0;j<4;j++) Cb[(size_t)r*Nn + col0 + tx*4 + j] = acc[i][j];
    }
}

// ---------------- generic GEMM: C = act(alpha * A[M,K] @ W[Nc,K]^T + bias), double-buffered ----------------
template<int ACT>
__global__ void __launch_bounds__(256) k_gemm(const float* __restrict__ A, const float* __restrict__ W,
                       const float* __restrict__ bias, float* __restrict__ C,
                       int M, int Nc, int K, float alpha){
    __shared__ float As[16][68];
    __shared__ float Ws[16][68];
    int tid = threadIdx.x;
    int tx = tid & 15, ty = tid >> 4;
    int row0 = blockIdx.y*64, col0 = blockIdx.x*64;
    float acc[4][4] = {};
    int lr = tid>>2, lk = (tid&3)*4;

    float4 pa = *(const float4*)(A + (size_t)(row0+lr)*K + lk);
    float4 pw = *(const float4*)(W + (size_t)(col0+lr)*K + lk);

    for(int k0=0;k0<K;k0+=16){
        As[lk  ][lr]=pa.x; As[lk+1][lr]=pa.y; As[lk+2][lr]=pa.z; As[lk+3][lr]=pa.w;
        Ws[lk  ][lr]=pw.x; Ws[lk+1][lr]=pw.y; Ws[lk+2][lr]=pw.z; Ws[lk+3][lr]=pw.w;
        __syncthreads();
        if(k0+16<K){
            pa = *(const float4*)(A + (size_t)(row0+lr)*K + k0+16+lk);
            pw = *(const float4*)(W + (size_t)(col0+lr)*K + k0+16+lk);
        }
#pragma unroll
        for(int k=0;k<16;k++){
            float4 av = *(const float4*)&As[k][ty*4];
            float4 wv = *(const float4*)&Ws[k][tx*4];
            float aa[4]={av.x,av.y,av.z,av.w};
            float ww[4]={wv.x,wv.y,wv.z,wv.w};
#pragma unroll
            for(int i=0;i<4;i++)
#pragma unroll
                for(int j=0;j<4;j++) acc[i][j] += aa[i]*ww[j];
        }
        __syncthreads();
    }
#pragma unroll
    for(int i=0;i<4;i++){
        int r = row0 + ty*4 + i;
#pragma unroll
        for(int j=0;j<4;j++){
            int c = col0 + tx*4 + j;
            float v = acc[i][j]*alpha;
            if(bias) v += bias[c];
            if(ACT==1) v = gelu_exact(v);
            C[(size_t)r*Nc + c] = v;
        }
    }
}

// ---------------- fused QKV GEMM: z selects weight/output/alpha ----------------
__global__ void __launch_bounds__(256) k_qkv(const float* __restrict__ A,
                      const float* __restrict__ qw, const float* __restrict__ kw,
                      const float* __restrict__ vw){
    const float* W; float* C; float alpha;
    if(blockIdx.z==0){ W=qw; C=g_q; alpha=0.25f; }
    else if(blockIdx.z==1){ W=kw; C=g_k; alpha=1.f; }
    else { W=vw; C=g_v; alpha=1.f; }

    __shared__ float As[16][68];
    __shared__ float Ws[16][68];
    int tid = threadIdx.x;
    int tx = tid & 15, ty = tid >> 4;
    int row0 = blockIdx.y*64, col0 = blockIdx.x*64;
    float acc[4][4] = {};
    int lr = tid>>2, lk = (tid&3)*4;

    float4 pa = *(const float4*)(A + (size_t)(row0+lr)*Ff + lk);
    float4 pw = *(const float4*)(W + (size_t)(col0+lr)*Ff + lk);

    for(int k0=0;k0<Ff;k0+=16){
        As[lk  ][lr]=pa.x; As[lk+1][lr]=pa.y; As[lk+2][lr]=pa.z; As[lk+3][lr]=pa.w;
        Ws[lk  ][lr]=pw.x; Ws[lk+1][lr]=pw.y; Ws[lk+2][lr]=pw.z; Ws[lk+3][lr]=pw.w;
        __syncthreads();
        if(k0+16<Ff){
            pa = *(const float4*)(A + (size_t)(row0+lr)*Ff + k0+16+lk);
            pw = *(const float4*)(W + (size_t)(col0+lr)*Ff + k0+16+lk);
        }
#pragma unroll
        for(int k=0;k<16;k++){
            float4 av = *(const float4*)&As[k][ty*4];
            float4 wv = *(const float4*)&Ws[k][tx*4];
            float aa[4]={av.x,av.y,av.z,av.w};
            float ww[4]={wv.x,wv.y,wv.z,wv.w};
#pragma unroll
            for(int i=0;i<4;i++)
#pragma unroll
                for(int j=0;j<4;j++) acc[i][j] += aa[i]*ww[j];
        }
        __syncthreads();
    }
#pragma unroll
    for(int i=0;i<4;i++){
        int r = row0 + ty*4 + i;
#pragma unroll
        for(int j=0;j<4;j++) C[(size_t)r*Ff + col0 + tx*4 + j] = acc[i][j]*alpha;
    }
}

// ---------------- degree & edge norm ----------------
__global__ void k_deg(const int* __restrict__ ei, int E){
    int e = blockIdx.x*blockDim.x + threadIdx.x;
    if(e<E) atomicAdd(&g_deg[ei[e]], 1.0f);
}
__global__ void k_enorm(const int* __restrict__ ei, int E){
    int e = blockIdx.x*blockDim.x + threadIdx.x;
    if(e>=E) return;
    float dr = g_deg[ei[e]]   + 1.0f;
    float dc = g_deg[ei[E+e]] + 1.0f;
    g_enorm[e] = rsqrtf(dr)*rsqrtf(dc);
}

// ---------------- CSR build (sort edges by target col) ----------------
__global__ void k_csr_count(const int* __restrict__ ei, int E){
    int e = blockIdx.x*blockDim.x + threadIdx.x;
    if(e<E) atomicAdd(&g_cnt[ei[E+e]], 1);
}
// exclusive scan over 4096 counts; single block of 1024 threads, 4 items each
__global__ void k_csr_scan(){
    __shared__ int wsum[32];
    int tid = threadIdx.x;
    int base = tid*4;
    int v0=g_cnt[base], v1=g_cnt[base+1], v2=g_cnt[base+2], v3=g_cnt[base+3];
    int sum = v0+v1+v2+v3;
    int lane = tid&31, wid = tid>>5;
    int x = sum;
#pragma unroll
    for(int o=1;o<32;o<<=1){ int y=__shfl_up_sync(0xffffffffu,x,o); if(lane>=o) x+=y; }
    if(lane==31) wsum[wid]=x;
    __syncthreads();
    if(wid==0){
        int t = wsum[lane];
#pragma unroll
        for(int o=1;o<32;o<<=1){ int y=__shfl_up_sync(0xffffffffu,t,o); if(lane>=o) t+=y; }
        wsum[lane]=t;
    }
    __syncthreads();
    int excl = x - sum + (wid ? wsum[wid-1] : 0);
    int run = excl;
    g_off[base]=run;   g_cur[base]=run;   run+=v0;
    g_off[base+1]=run; g_cur[base+1]=run; run+=v1;
    g_off[base+2]=run; g_cur[base+2]=run; run+=v2;
    g_off[base+3]=run; g_cur[base+3]=run; run+=v3;
    if(tid==1023) g_off[BNn]=run;
}
__global__ void k_csr_scatter(const int* __restrict__ ei, int E){
    int e = blockIdx.x*blockDim.x + threadIdx.x;
    if(e>=E) return;
    int pos = atomicAdd(&g_cur[ei[E+e]], 1);
    g_elist[pos] = e;
}

// ---------------- fused GCN: gather messages (CSR) + node update + LN + residual ----------------
// one warp per node, 8 warps per block
__global__ void __launch_bounds__(256) k_gcn(const int* __restrict__ ei, int E,
                      const float* __restrict__ eattr, const float* __restrict__ ew,
                      const float* __restrict__ gg, const float* __restrict__ gb,
                      const float* __restrict__ emb, const int* __restrict__ root){
    __shared__ float ws[128*7];
    int tid = threadIdx.x;
    for(int i=tid;i<128*7;i+=256) ws[i]=ew[i];
    __syncthreads();

    int warp = tid>>5, lane = tid&31;
    int n = blockIdx.x*8 + warp;
    float acc[4] = {0.f,0.f,0.f,0.f};
    int beg = g_off[n], end = g_off[n+1];
    for(int i=beg;i<end;i++){
        int e = g_elist[i];
        int row = ei[e];
        float en = g_enorm[e];
        float eav = (lane<7) ? eattr[(size_t)e*7+lane] : 0.f;
        float ea[7];
#pragma unroll
        for(int j=0;j<7;j++) ea[j] = __shfl_sync(0xffffffffu, eav, j);
#pragma unroll
        for(int c=0;c<4;c++){
            int f = c*32 + lane;
            float s = g_h[(size_t)row*Ff + f];
            const float* w = &ws[f*7];
#pragma unroll
            for(int j=0;j<7;j++) s += ea[j]*w[j];
            acc[c] += fmaxf(s, 0.f)*en;
        }
    }
    // node update + LN + relu + residual add
    float dvinv = 1.0f / (g_deg[n] + 1.0f);
    const float* er = emb + root[n]*Ff;
    float t[4]; float s=0.f;
#pragma unroll
    for(int c=0;c<4;c++){
        int f = c*32 + lane;
        float hv = g_h[(size_t)n*Ff+f] + er[f];
        t[c] = acc[c] + fmaxf(hv,0.f)*dvinv;
        s += t[c];
    }
    float mean = warpsum(s) * (1.f/Ff);
    float vv=0.f;
#pragma unroll
    for(int c=0;c<4;c++){ float d=t[c]-mean; vv += d*d; }
    float inv = rsqrtf(warpsum(vv)*(1.f/Ff) + 1e-5f);
#pragma unroll
    for(int c=0;c<4;c++){
        int f = c*32 + lane;
        float y = (t[c]-mean)*inv*gg[f] + gb[f];
        g_out[(size_t)n*Ff+f] += fmaxf(y, 0.f);
    }
}

// ---------------- residual + layernorm ----------------
__global__ void k_addln(const float* __restrict__ a, const float* __restrict__ res,
                        const float* __restrict__ gg, const float* __restrict__ gb,
                        float* __restrict__ out){
    int warp = threadIdx.x>>5, lane = threadIdx.x&31;
    int n = blockIdx.x*8 + warp;
    float t[4]; float s=0;
#pragma unroll
    for(int c=0;c<4;c++){
        int f = c*32 + lane;
        float v = a[(size_t)n*Ff+f];
        if(res) v += res[(size_t)n*Ff+f];
        t[c]=v; s+=v;
    }
    float mean = warpsum(s) * (1.f/Ff);
    float vv=0;
#pragma unroll
    for(int c=0;c<4;c++){ float d=t[c]-mean; vv += d*d; }
    float inv = rsqrtf(warpsum(vv)*(1.f/Ff) + 1e-5f);
#pragma unroll
    for(int c=0;c<4;c++){
        int f = c*32 + lane;
        out[(size_t)n*Ff+f] = (t[c]-mean)*inv*gg[f] + gb[f];
    }
}

// ---------------- fused attention, 4-wide m unroll ----------------
__global__ void __launch_bounds__(256) k_attn(const float* __restrict__ mclw, const int* __restrict__ n_counts){
    int h = blockIdx.x, b = blockIdx.y;
    __shared__ float ks[Nn][DHh];
    __shared__ float vs[Nn][DHh];
    int tid = threadIdx.x;

#pragma unroll
    for(int c=0;c<4;c++){
        *(float4*)&ks[tid][c*4] = *(const float4*)(g_k + ((size_t)(b*Nn+tid)*Ff) + h*DHh + c*4);
        *(float4*)&vs[tid][c*4] = *(const float4*)(g_v + ((size_t)(b*Nn+tid)*Ff) + h*DHh + c*4);
    }
    __syncthreads();

    int n  = tid;
    int nc = n_counts[b];
    bool vn = (n < nc);
    float w = mclw[h];
    const float* mrow = g_r + ((size_t)(b*Nn+n))*Nn;

    float qr[DHh];
#pragma unroll
    for(int d=0;d<DHh;d++) qr[d] = g_q[((size_t)(b*Nn+n))*Ff + h*DHh + d];

    float mx = -1e30f, sum = 0.f, acc[DHh] = {};
    for(int m=0;m<Nn;m+=4){
        float s0=0.f,s1=0.f,s2=0.f,s3=0.f;
#pragma unroll
        for(int d=0;d<DHh;d++){
            float qd = qr[d];
            s0 += qd*ks[m  ][d];
            s1 += qd*ks[m+1][d];
            s2 += qd*ks[m+2][d];
            s3 += qd*ks[m+3][d];
        }
        float4 mr = *(const float4*)(mrow + m);
        s0 += ((vn && (m  <nc)) ? 0.f : -1024.f) + mr.x*w;
        s1 += ((vn && (m+1<nc)) ? 0.f : -1024.f) + mr.y*w;
        s2 += ((vn && (m+2<nc)) ? 0.f : -1024.f) + mr.z*w;
        s3 += ((vn && (m+3<nc)) ? 0.f : -1024.f) + mr.w*w;

        float gmax = fmaxf(fmaxf(s0,s1), fmaxf(s2,s3));
        if(gmax > mx){
            float sc = __expf(mx - gmax);
            sum *= sc;
#pragma unroll
            for(int d=0;d<DHh;d++) acc[d] *= sc;
            mx = gmax;
        }
        float p0=__expf(s0-mx), p1=__expf(s1-mx), p2=__expf(s2-mx), p3=__expf(s3-mx);
        sum += p0+p1+p2+p3;
#pragma unroll
        for(int d=0;d<DHh;d++)
            acc[d] += p0*vs[m][d] + p1*vs[m+1][d] + p2*vs[m+2][d] + p3*vs[m+3][d];
    }
    float inv = 1.f/sum;
#pragma unroll
    for(int d=0;d<DHh;d++) g_o[((size_t)(b*Nn+n))*Ff + h*DHh + d] = acc[d]*inv;
}

// ---------------- host ----------------
extern "C" void kernel_launch(void* const* d_in, const int* in_sizes, int n_in,
                              void* d_out, int out_size){
    (void)n_in; (void)out_size;
    const float* input_x      = (const float*)d_in[0];
    const float* edge_attr    = (const float*)d_in[1];
    const float* gcn_lin_w    = (const float*)d_in[2];
    const float* gcn_root_emb = (const float*)d_in[3];
    const float* gcn_edge_w   = (const float*)d_in[4];
    const float* gcn_norm_g   = (const float*)d_in[5];
    const float* gcn_norm_b   = (const float*)d_in[6];
    const float* ln_in_g      = (const float*)d_in[7];
    const float* ln_in_b      = (const float*)d_in[8];
    const float* ln_ffn_g     = (const float*)d_in[9];
    const float* ln_ffn_b     = (const float*)d_in[10];
    const float* mcl_w        = (const float*)d_in[11];
    const float* q_w          = (const float*)d_in[12];
    const float* k_w          = (const float*)d_in[13];
    const float* v_w          = (const float*)d_in[14];
    const float* merge_w      = (const float*)d_in[15];
    const float* merge_b      = (const float*)d_in[16];
    const float* ffn_w1       = (const float*)d_in[17];
    const float* ffn_b1       = (const float*)d_in[18];
    const float* ffn_w2       = (const float*)d_in[19];
    const float* ffn_b2       = (const float*)d_in[20];
    const float* final_g      = (const float*)d_in[21];
    const float* final_b      = (const float*)d_in[22];
    const int*   edge_index   = (const int*)d_in[23];
    const int*   n_counts     = (const int*)d_in[24];
    const int*   root         = (const int*)d_in[25];
    int E = in_sizes[23] / 2;

    float *m_p,*r_p,*t_p,*deg_p,*out_p,*h_p,*q_p,*k_p,*v_p,*o_p,*x_p,*f1_p;
    int *cnt_p;
    cudaGetSymbolAddress((void**)&m_p,   g_m);
    cudaGetSymbolAddress((void**)&r_p,   g_r);
    cudaGetSymbolAddress((void**)&t_p,   g_t);
    cudaGetSymbolAddress((void**)&deg_p, g_deg);
    cudaGetSymbolAddress((void**)&out_p, g_out);
    cudaGetSymbolAddress((void**)&h_p,   g_h);
    cudaGetSymbolAddress((void**)&q_p,   g_q);
    cudaGetSymbolAddress((void**)&k_p,   g_k);
    cudaGetSymbolAddress((void**)&v_p,   g_v);
    cudaGetSymbolAddress((void**)&o_p,   g_o);
    cudaGetSymbolAddress((void**)&x_p,   g_x);
    cudaGetSymbolAddress((void**)&f1_p,  g_f1);
    cudaGetSymbolAddress((void**)&cnt_p, g_cnt);

    // ---- adjacency + MCL ----
    k_zero<<<(Bb*Nn*Nn+255)/256,256>>>(m_p, Bb*Nn*Nn);
    k_build_adj<<<(E+255)/256,256>>>(edge_index, E);
    k_selfloop<<<(BNn+255)/256,256>>>(n_counts);
    k_rownorm<<<Bb*Nn/4,256>>>(m_p, m_p, 0);
    const float* rcur = m_p;
    for(int i=0;i<6;i++){
        k_bmm<<<dim3(4,4,Bb),256>>>(m_p, rcur, t_p);
        k_rownorm<<<Bb*Nn/4,256>>>(t_p, r_p, ((i+1)%3==0)?1:0);
        rcur = r_p;
    }

    // ---- degree / edge norm ----
    k_zero<<<(BNn+255)/256,256>>>(deg_p, BNn);
    k_deg<<<(E+255)/256,256>>>(edge_index, E);
    k_enorm<<<(E+255)/256,256>>>(edge_index, E);

    // ---- CSR build (edges sorted by target) ----
    k_zeroi<<<(BNn+255)/256,256>>>(cnt_p, BNn);
    k_csr_count<<<(E+255)/256,256>>>(edge_index, E);
    k_csr_scan<<<1,1024>>>();
    k_csr_scatter<<<(E+255)/256,256>>>(edge_index, E);

    // ---- out = input ----
    cudaMemcpyAsync(out_p, input_x, (size_t)BNn*Ff*sizeof(float), cudaMemcpyDeviceToDevice, 0);

    dim3 g128(Ff/64, BNn/64);        // (2,64)
    dim3 g256(2*Ff/64, BNn/64);      // (4,64)
    dim3 gqkv(Ff/64, BNn/64, 3);     // (2,64,3)

    for(int l=0;l<Ll;l++){
        // ---- GCN ----
        k_gemm<0><<<g128,256>>>(out_p, gcn_lin_w + (size_t)l*Ff*Ff, nullptr, h_p, BNn, Ff, Ff, 1.f);
        k_gcn<<<BNn/8,256>>>(edge_index, E, edge_attr, gcn_edge_w + (size_t)l*Ff*7,
                             gcn_norm_g + l*Ff, gcn_norm_b + l*Ff,
                             gcn_root_emb + (size_t)l*2*Ff, root);

        // ---- attention ----
        k_qkv<<<gqkv,256>>>(out_p, q_w + (size_t)l*Ff*Ff, k_w + (size_t)l*Ff*Ff, v_w + (size_t)l*Ff*Ff);
        k_attn<<<dim3(Hh,Bb),256>>>(mcl_w + l*Hh, n_counts);
        k_gemm<0><<<g128,256>>>(o_p, merge_w + (size_t)l*Ff*Ff, merge_b + l*Ff, h_p, BNn, Ff, Ff, 1.f);
        k_addln<<<BNn/8,256>>>(h_p, out_p, ln_in_g + l*Ff, ln_in_b + l*Ff, x_p);

        // ---- FFN ----
        k_gemm<1><<<g256,256>>>(x_p, ffn_w1 + (size_t)l*2*Ff*Ff, ffn_b1 + (size_t)l*2*Ff,
                                f1_p, BNn, 2*Ff, Ff, 1.f);
        k_gemm<0><<<g128,256>>>(f1_p, ffn_w2 + (size_t)l*Ff*2*Ff, ffn_b2 + l*Ff,
                                h_p, BNn, Ff, 2*Ff, 1.f);
        k_addln<<<BNn/8,256>>>(x_p, h_p, ln_ffn_g + l*Ff, ln_ffn_b + l*Ff, out_p);
    }

    // ---- final layernorm ----
    k_addln<<<BNn/8,256>>>(out_p, nullptr, final_g, final_b, (float*)d_out);
}

// round 4
// speedup vs baseline: 1.4528x; 1.1033x over previous
#include <cuda_runtime.h>
#include <math.h>
#include <stdint.h>

#define Bb   16
#define Nn   256
#define Ff   128
#define Hh   8
#define DHh  16
#define Ll   9
#define BNn  4096
#define Emax 65536

// ---------------- scratch (device globals; no allocations) ----------------
__device__ float g_m[Bb*Nn*Nn];
__device__ float g_r[Bb*Nn*Nn];
__device__ float g_t[Bb*Nn*Nn];
__device__ float g_deg[BNn];
__device__ float g_enorm[Emax];
__device__ float g_out[BNn*Ff];
__device__ float g_h[BNn*Ff];
__device__ float g_q[BNn*Ff];
__device__ float g_k[BNn*Ff];
__device__ float g_v[BNn*Ff];
__device__ float g_o[BNn*Ff];
__device__ float g_x[BNn*Ff];
__device__ float g_f1[BNn*2*Ff];
// CSR by col
__device__ int g_cnt[BNn];
__device__ int g_off[BNn+1];
__device__ int g_cur[BNn];
__device__ int g_elist[Emax];

__device__ __forceinline__ float warpsum(float v){
#pragma unroll
    for(int o=16;o;o>>=1) v += __shfl_xor_sync(0xffffffffu, v, o);
    return v;
}

__device__ __forceinline__ float gelu_exact(float x){
    return 0.5f*x*(1.0f + erff(x*0.70710678118654752f));
}

// ---------------- tf32 tensor-core GEMM machinery (3xTF32 compensated) ----------------
__device__ __forceinline__ uint32_t f2tf32(float x){
    uint32_t u; asm("cvt.rna.tf32.f32 %0, %1;" : "=r"(u) : "f"(x)); return u;
}
__device__ __forceinline__ void split1(float x, uint32_t& hi, uint32_t& lo){
    hi = f2tf32(x);
    lo = __float_as_uint(x - __uint_as_float(hi));   // exact; HW truncates lo to tf32 in MMA
}
// swizzled smem index for a 64x16-word tile: conflict-free frag loads AND stores
__device__ __forceinline__ int swz(int r, int k){
    return ((r>>1)<<5) + ((r&1)<<4) + (k ^ (((r>>1)&3)<<2));
}
__device__ __forceinline__ void mma_tf32(float* c, uint32_t a0,uint32_t a1,uint32_t a2,uint32_t a3,
                                         uint32_t b0,uint32_t b1){
    asm volatile("mma.sync.aligned.m16n8k8.row.col.f32.tf32.tf32.f32 "
        "{%0,%1,%2,%3},{%4,%5,%6,%7},{%8,%9},{%0,%1,%2,%3};\n"
        : "+f"(c[0]),"+f"(c[1]),"+f"(c[2]),"+f"(c[3])
        : "r"(a0),"r"(a1),"r"(a2),"r"(a3),"r"(b0),"r"(b1));
}

// C[64x64 tile] = act(alpha * A[M,K] @ W[Nc,K]^T + bias).  128 threads, 4 warps of 32x32.
template<int ACT>
__device__ __forceinline__ void gemm_tc_tile(const float* __restrict__ A, const float* __restrict__ W,
        const float* __restrict__ bias, float* __restrict__ C,
        int Nc, int K, float alpha, int bx, int by)
{
    __shared__ __align__(16) uint32_t As[2][64*16];   // [0]=hi, [1]=lo
    __shared__ __align__(16) uint32_t Ws[2][64*16];
    int tid = threadIdx.x;
    int wid = tid>>5, lane = tid&31, gid = lane>>2, tig = lane&3;
    int wm = (wid&1)*32, wn = (wid>>1)*32;
    int row0 = by*64, col0 = bx*64;
    int lr = tid>>2, lk = (tid&3)*4;

    float acc[2][4][4];
#pragma unroll
    for(int i=0;i<2;i++)
#pragma unroll
    for(int j=0;j<4;j++)
#pragma unroll
    for(int t=0;t<4;t++) acc[i][j][t]=0.f;

    const float* Ap = A + (size_t)(row0+lr)*K + lk;
    const float* Wp = W + (size_t)(col0+lr)*K + lk;
    float4 pa0 = *(const float4*)(Ap);
    float4 pa1 = *(const float4*)(Ap + (size_t)32*K);
    float4 pw0 = *(const float4*)(Wp);
    float4 pw1 = *(const float4*)(Wp + (size_t)32*K);

    for(int k0=0;k0<K;k0+=16){
        uint4 h, l;
        split1(pa0.x,h.x,l.x); split1(pa0.y,h.y,l.y); split1(pa0.z,h.z,l.z); split1(pa0.w,h.w,l.w);
        *(uint4*)&As[0][swz(lr,lk)] = h;  *(uint4*)&As[1][swz(lr,lk)] = l;
        split1(pa1.x,h.x,l.x); split1(pa1.y,h.y,l.y); split1(pa1.z,h.z,l.z); split1(pa1.w,h.w,l.w);
        *(uint4*)&As[0][swz(lr+32,lk)] = h;  *(uint4*)&As[1][swz(lr+32,lk)] = l;
        split1(pw0.x,h.x,l.x); split1(pw0.y,h.y,l.y); split1(pw0.z,h.z,l.z); split1(pw0.w,h.w,l.w);
        *(uint4*)&Ws[0][swz(lr,lk)] = h;  *(uint4*)&Ws[1][swz(lr,lk)] = l;
        split1(pw1.x,h.x,l.x); split1(pw1.y,h.y,l.y); split1(pw1.z,h.z,l.z); split1(pw1.w,h.w,l.w);
        *(uint4*)&Ws[0][swz(lr+32,lk)] = h;  *(uint4*)&Ws[1][swz(lr+32,lk)] = l;
        __syncthreads();

        if(k0+16<K){
            pa0 = *(const float4*)(Ap + k0+16);
            pa1 = *(const float4*)(Ap + (size_t)32*K + k0+16);
            pw0 = *(const float4*)(Wp + k0+16);
            pw1 = *(const float4*)(Wp + (size_t)32*K + k0+16);
        }

#pragma unroll
        for(int s=0;s<2;s++){
            int ks = s*8 + tig;
            uint32_t afh[2][4], afl[2][4], bfh[4][2], bfl[4][2];
#pragma unroll
            for(int i=0;i<2;i++){
                int r = wm + 16*i + gid;
                afh[i][0]=As[0][swz(r,  ks)];   afl[i][0]=As[1][swz(r,  ks)];
                afh[i][1]=As[0][swz(r+8,ks)];   afl[i][1]=As[1][swz(r+8,ks)];
                afh[i][2]=As[0][swz(r,  ks+4)]; afl[i][2]=As[1][swz(r,  ks+4)];
                afh[i][3]=As[0][swz(r+8,ks+4)]; afl[i][3]=As[1][swz(r+8,ks+4)];
            }
#pragma unroll
            for(int j=0;j<4;j++){
                int n = wn + 8*j + gid;
                bfh[j][0]=Ws[0][swz(n,ks)];     bfl[j][0]=Ws[1][swz(n,ks)];
                bfh[j][1]=Ws[0][swz(n,ks+4)];   bfl[j][1]=Ws[1][swz(n,ks+4)];
            }
#pragma unroll
            for(int i=0;i<2;i++)
#pragma unroll
            for(int j=0;j<4;j++){
                // small terms first, then hi*hi
                mma_tf32(acc[i][j], afl[i][0],afl[i][1],afl[i][2],afl[i][3], bfh[j][0],bfh[j][1]);
                mma_tf32(acc[i][j], afh[i][0],afh[i][1],afh[i][2],afh[i][3], bfl[j][0],bfl[j][1]);
                mma_tf32(acc[i][j], afh[i][0],afh[i][1],afh[i][2],afh[i][3], bfh[j][0],bfh[j][1]);
            }
        }
        __syncthreads();
    }

#pragma unroll
    for(int i=0;i<2;i++){
        int rg = row0 + wm + 16*i + gid;
#pragma unroll
        for(int j=0;j<4;j++){
            int cg = col0 + wn + 8*j + tig*2;
            float b0v = bias ? bias[cg]   : 0.f;
            float b1v = bias ? bias[cg+1] : 0.f;
            float v0 = acc[i][j][0]*alpha + b0v;
            float v1 = acc[i][j][1]*alpha + b1v;
            float v2 = acc[i][j][2]*alpha + b0v;
            float v3 = acc[i][j][3]*alpha + b1v;
            if(ACT==1){ v0=gelu_exact(v0); v1=gelu_exact(v1); v2=gelu_exact(v2); v3=gelu_exact(v3); }
            *(float2*)&C[(size_t)rg*Nc + cg]     = make_float2(v0,v1);
            *(float2*)&C[(size_t)(rg+8)*Nc + cg] = make_float2(v2,v3);
        }
    }
}

template<int ACT>
__global__ void __launch_bounds__(128) k_gemm_tc(const float* __restrict__ A, const float* __restrict__ W,
        const float* __restrict__ bias, float* __restrict__ C, int Nc, int K, float alpha){
    gemm_tc_tile<ACT>(A, W, bias, C, Nc, K, alpha, blockIdx.x, blockIdx.y);
}

__global__ void __launch_bounds__(128) k_qkv_tc(const float* __restrict__ A,
        const float* __restrict__ qw, const float* __restrict__ kw, const float* __restrict__ vw){
    const float* W; float* C; float alpha;
    if(blockIdx.z==0){ W=qw; C=g_q; alpha=0.25f; }
    else if(blockIdx.z==1){ W=kw; C=g_k; alpha=1.f; }
    else { W=vw; C=g_v; alpha=1.f; }
    gemm_tc_tile<0>(A, W, nullptr, C, Ff, Ff, alpha, blockIdx.x, blockIdx.y);
}

// ---------------- simple utility kernels ----------------
__global__ void k_zero(float* __restrict__ p, int n){
    int i = blockIdx.x*blockDim.x + threadIdx.x;
    if(i<n) p[i]=0.f;
}
__global__ void k_zeroi(int* __restrict__ p, int n){
    int i = blockIdx.x*blockDim.x + threadIdx.x;
    if(i<n) p[i]=0;
}

__global__ void k_build_adj(const int* __restrict__ ei, int E){
    int e = blockIdx.x*blockDim.x + threadIdx.x;
    if(e>=E) return;
    int row = ei[e], col = ei[E+e];
    int eb = row/Nn, es = row%Nn, et = col%Nn;
    g_m[(eb*Nn+es)*Nn + et] = 1.0f;
}

__global__ void k_selfloop(const int* __restrict__ n_counts){
    int i = blockIdx.x*blockDim.x + threadIdx.x;
    if(i>=BNn) return;
    int b = i/Nn, n = i%Nn;
    if(n < n_counts[b]) g_m[(b*Nn+n)*Nn + n] = 1.0f;
}

// per-row normalize (optionally x^6 first).  4 rows/block, float4.
__global__ void k_rownorm(const float* __restrict__ src, float* __restrict__ dst, int pow6){
    int tid = threadIdx.x;
    int rloc = tid >> 6;
    int sub  = tid & 63;
    int row  = blockIdx.x*4 + rloc;
    float4 v = *(const float4*)(src + (size_t)row*Nn + sub*4);
    if(pow6){
        float a2;
        a2=v.x*v.x; v.x=a2*a2*a2;
        a2=v.y*v.y; v.y=a2*a2*a2;
        a2=v.z*v.z; v.z=a2*a2*a2;
        a2=v.w*v.w; v.w=a2*a2*a2;
    }
    float s = v.x+v.y+v.z+v.w;
    s = warpsum(s);
    __shared__ float hs[8];
    if((tid&31)==0) hs[tid>>5] = s;
    __syncthreads();
    float tot = hs[rloc*2] + hs[rloc*2+1];
    float inv = 1.0f/(tot + 1e-6f);
    v.x*=inv; v.y*=inv; v.z*=inv; v.w*=inv;
    *(float4*)(dst + (size_t)row*Nn + sub*4) = v;
}

// ---------------- batched NxN @ NxN (MCL), f32, double-buffered ----------------
__global__ void __launch_bounds__(256) k_bmm(const float* __restrict__ A, const float* __restrict__ B, float* __restrict__ C){
    int b = blockIdx.z;
    const float* Ab = A + (size_t)b*Nn*Nn;
    const float* Bp = B + (size_t)b*Nn*Nn;
    float*       Cb = C + (size_t)b*Nn*Nn;

    __shared__ float As[16][68];
    __shared__ float Bs[16][68];
    int tid = threadIdx.x;
    int tx = tid & 15, ty = tid >> 4;
    int row0 = blockIdx.y*64, col0 = blockIdx.x*64;
    float acc[4][4] = {};

    int lr = tid>>2, lk = (tid&3)*4;
    int bk = tid>>4, bc = (tid&15)*4;

    float4 pa = *(const float4*)(Ab + (size_t)(row0+lr)*Nn + lk);
    float4 pb = *(const float4*)(Bp + (size_t)bk*Nn + col0+bc);

    for(int k0=0;k0<Nn;k0+=16){
        As[lk  ][lr]=pa.x; As[lk+1][lr]=pa.y; As[lk+2][lr]=pa.z; As[lk+3][lr]=pa.w;
        *(float4*)&Bs[bk][bc] = pb;
        __syncthreads();
        if(k0+16<Nn){
            pa = *(const float4*)(Ab + (size_t)(row0+lr)*Nn + k0+16+lk);
            pb = *(const float4*)(Bp + (size_t)(k0+16+bk)*Nn + col0+bc);
        }
#pragma unroll
        for(int k=0;k<16;k++){
            float4 av = *(const float4*)&As[k][ty*4];
            float4 wv = *(const float4*)&Bs[k][tx*4];
            float aa[4]={av.x,av.y,av.z,av.w};
            float ww[4]={wv.x,wv.y,wv.z,wv.w};
#pragma unroll
            for(int i=0;i<4;i++)
#pragma unroll
                for(int j=0;j<4;j++) acc[i][j] += aa[i]*ww[j];
        }
        __syncthreads();
    }
#pragma unroll
    for(int i=0;i<4;i++){
        int r = row0 + ty*4 + i;
#pragma unroll
        for(int j=0;j<4;j++) Cb[(size_t)r*Nn + col0 + tx*4 + j] = acc[i][j];
    }
}

// ---------------- degree & edge norm ----------------
__global__ void k_deg(const int* __restrict__ ei, int E){
    int e = blockIdx.x*blockDim.x + threadIdx.x;
    if(e<E) atomicAdd(&g_deg[ei[e]], 1.0f);
}
__global__ void k_enorm(const int* __restrict__ ei, int E){
    int e = blockIdx.x*blockDim.x + threadIdx.x;
    if(e>=E) return;
    float dr = g_deg[ei[e]]   + 1.0f;
    float dc = g_deg[ei[E+e]] + 1.0f;
    g_enorm[e] = rsqrtf(dr)*rsqrtf(dc);
}

// ---------------- CSR build (sort edges by target col) ----------------
__global__ void k_csr_count(const int* __restrict__ ei, int E){
    int e = blockIdx.x*blockDim.x + threadIdx.x;
    if(e<E) atomicAdd(&g_cnt[ei[E+e]], 1);
}
__global__ void k_csr_scan(){
    __shared__ int wsum[32];
    int tid = threadIdx.x;
    int base = tid*4;
    int v0=g_cnt[base], v1=g_cnt[base+1], v2=g_cnt[base+2], v3=g_cnt[base+3];
    int sum = v0+v1+v2+v3;
    int lane = tid&31, wid = tid>>5;
    int x = sum;
#pragma unroll
    for(int o=1;o<32;o<<=1){ int y=__shfl_up_sync(0xffffffffu,x,o); if(lane>=o) x+=y; }
    if(lane==31) wsum[wid]=x;
    __syncthreads();
    if(wid==0){
        int t = wsum[lane];
#pragma unroll
        for(int o=1;o<32;o<<=1){ int y=__shfl_up_sync(0xffffffffu,t,o); if(lane>=o) t+=y; }
        wsum[lane]=t;
    }
    __syncthreads();
    int excl = x - sum + (wid ? wsum[wid-1] : 0);
    int run = excl;
    g_off[base]=run;   g_cur[base]=run;   run+=v0;
    g_off[base+1]=run; g_cur[base+1]=run; run+=v1;
    g_off[base+2]=run; g_cur[base+2]=run; run+=v2;
    g_off[base+3]=run; g_cur[base+3]=run; run+=v3;
    if(tid==1023) g_off[BNn]=run;
}
__global__ void k_csr_scatter(const int* __restrict__ ei, int E){
    int e = blockIdx.x*blockDim.x + threadIdx.x;
    if(e>=E) return;
    int pos = atomicAdd(&g_cur[ei[E+e]], 1);
    g_elist[pos] = e;
}

// ---------------- fused GCN: gather (CSR) + node update + LN + residual ----------------
__global__ void __launch_bounds__(256) k_gcn(const int* __restrict__ ei, int E,
                      const float* __restrict__ eattr, const float* __restrict__ ew,
                      const float* __restrict__ gg, const float* __restrict__ gb,
                      const float* __restrict__ emb, const int* __restrict__ root){
    __shared__ float ws[128*7];
    int tid = threadIdx.x;
    for(int i=tid;i<128*7;i+=256) ws[i]=ew[i];
    __syncthreads();

    int warp = tid>>5, lane = tid&31;
    int n = blockIdx.x*8 + warp;
    float acc[4] = {0.f,0.f,0.f,0.f};
    int beg = g_off[n], end = g_off[n+1];
    for(int i=beg;i<end;i++){
        int e = g_elist[i];
        int row = ei[e];
        float en = g_enorm[e];
        float eav = (lane<7) ? eattr[(size_t)e*7+lane] : 0.f;
        float ea[7];
#pragma unroll
        for(int j=0;j<7;j++) ea[j] = __shfl_sync(0xffffffffu, eav, j);
#pragma unroll
        for(int c=0;c<4;c++){
            int f = c*32 + lane;
            float s = g_h[(size_t)row*Ff + f];
            const float* w = &ws[f*7];
#pragma unroll
            for(int j=0;j<7;j++) s += ea[j]*w[j];
            acc[c] += fmaxf(s, 0.f)*en;
        }
    }
    float dvinv = 1.0f / (g_deg[n] + 1.0f);
    const float* er = emb + root[n]*Ff;
    float t[4]; float s=0.f;
#pragma unroll
    for(int c=0;c<4;c++){
        int f = c*32 + lane;
        float hv = g_h[(size_t)n*Ff+f] + er[f];
        t[c] = acc[c] + fmaxf(hv,0.f)*dvinv;
        s += t[c];
    }
    float mean = warpsum(s) * (1.f/Ff);
    float vv=0.f;
#pragma unroll
    for(int c=0;c<4;c++){ float d=t[c]-mean; vv += d*d; }
    float inv = rsqrtf(warpsum(vv)*(1.f/Ff) + 1e-5f);
#pragma unroll
    for(int c=0;c<4;c++){
        int f = c*32 + lane;
        float y = (t[c]-mean)*inv*gg[f] + gb[f];
        g_out[(size_t)n*Ff+f] += fmaxf(y, 0.f);
    }
}

// ---------------- residual + layernorm ----------------
__global__ void k_addln(const float* __restrict__ a, const float* __restrict__ res,
                        const float* __restrict__ gg, const float* __restrict__ gb,
                        float* __restrict__ out){
    int warp = threadIdx.x>>5, lane = threadIdx.x&31;
    int n = blockIdx.x*8 + warp;
    float t[4]; float s=0;
#pragma unroll
    for(int c=0;c<4;c++){
        int f = c*32 + lane;
        float v = a[(size_t)n*Ff+f];
        if(res) v += res[(size_t)n*Ff+f];
        t[c]=v; s+=v;
    }
    float mean = warpsum(s) * (1.f/Ff);
    float vv=0;
#pragma unroll
    for(int c=0;c<4;c++){ float d=t[c]-mean; vv += d*d; }
    float inv = rsqrtf(warpsum(vv)*(1.f/Ff) + 1e-5f);
#pragma unroll
    for(int c=0;c<4;c++){
        int f = c*32 + lane;
        out[(size_t)n*Ff+f] = (t[c]-mean)*inv*gg[f] + gb[f];
    }
}

// ---------------- fused attention, 4-wide m unroll ----------------
__global__ void __launch_bounds__(256) k_attn(const float* __restrict__ mclw, const int* __restrict__ n_counts){
    int h = blockIdx.x, b = blockIdx.y;
    __shared__ float ks[Nn][DHh];
    __shared__ float vs[Nn][DHh];
    int tid = threadIdx.x;

#pragma unroll
    for(int c=0;c<4;c++){
        *(float4*)&ks[tid][c*4] = *(const float4*)(g_k + ((size_t)(b*Nn+tid)*Ff) + h*DHh + c*4);
        *(float4*)&vs[tid][c*4] = *(const float4*)(g_v + ((size_t)(b*Nn+tid)*Ff) + h*DHh + c*4);
    }
    __syncthreads();

    int n  = tid;
    int nc = n_counts[b];
    bool vn = (n < nc);
    float w = mclw[h];
    const float* mrow = g_r + ((size_t)(b*Nn+n))*Nn;

    float qr[DHh];
#pragma unroll
    for(int d=0;d<DHh;d++) qr[d] = g_q[((size_t)(b*Nn+n))*Ff + h*DHh + d];

    float mx = -1e30f, sum = 0.f, acc[DHh] = {};
    for(int m=0;m<Nn;m+=4){
        float s0=0.f,s1=0.f,s2=0.f,s3=0.f;
#pragma unroll
        for(int d=0;d<DHh;d++){
            float qd = qr[d];
            s0 += qd*ks[m  ][d];
            s1 += qd*ks[m+1][d];
            s2 += qd*ks[m+2][d];
            s3 += qd*ks[m+3][d];
        }
        float4 mr = *(const float4*)(mrow + m);
        s0 += ((vn && (m  <nc)) ? 0.f : -1024.f) + mr.x*w;
        s1 += ((vn && (m+1<nc)) ? 0.f : -1024.f) + mr.y*w;
        s2 += ((vn && (m+2<nc)) ? 0.f : -1024.f) + mr.z*w;
        s3 += ((vn && (m+3<nc)) ? 0.f : -1024.f) + mr.w*w;

        float gmax = fmaxf(fmaxf(s0,s1), fmaxf(s2,s3));
        if(gmax > mx){
            float sc = __expf(mx - gmax);
            sum *= sc;
#pragma unroll
            for(int d=0;d<DHh;d++) acc[d] *= sc;
            mx = gmax;
        }
        float p0=__expf(s0-mx), p1=__expf(s1-mx), p2=__expf(s2-mx), p3=__expf(s3-mx);
        sum += p0+p1+p2+p3;
#pragma unroll
        for(int d=0;d<DHh;d++)
            acc[d] += p0*vs[m][d] + p1*vs[m+1][d] + p2*vs[m+2][d] + p3*vs[m+3][d];
    }
    float inv = 1.f/sum;
#pragma unroll
    for(int d=0;d<DHh;d++) g_o[((size_t)(b*Nn+n))*Ff + h*DHh + d] = acc[d]*inv;
}

// ---------------- host ----------------
extern "C" void kernel_launch(void* const* d_in, const int* in_sizes, int n_in,
                              void* d_out, int out_size){
    (void)n_in; (void)out_size;
    const float* input_x      = (const float*)d_in[0];
    const float* edge_attr    = (const float*)d_in[1];
    const float* gcn_lin_w    = (const float*)d_in[2];
    const float* gcn_root_emb = (const float*)d_in[3];
    const float* gcn_edge_w   = (const float*)d_in[4];
    const float* gcn_norm_g   = (const float*)d_in[5];
    const float* gcn_norm_b   = (const float*)d_in[6];
    const float* ln_in_g      = (const float*)d_in[7];
    const float* ln_in_b      = (const float*)d_in[8];
    const float* ln_ffn_g     = (const float*)d_in[9];
    const float* ln_ffn_b     = (const float*)d_in[10];
    const float* mcl_w        = (const float*)d_in[11];
    const float* q_w          = (const float*)d_in[12];
    const float* k_w          = (const float*)d_in[13];
    const float* v_w          = (const float*)d_in[14];
    const float* merge_w      = (const float*)d_in[15];
    const float* merge_b      = (const float*)d_in[16];
    const float* ffn_w1       = (const float*)d_in[17];
    const float* ffn_b1       = (const float*)d_in[18];
    const float* ffn_w2       = (const float*)d_in[19];
    const float* ffn_b2       = (const float*)d_in[20];
    const float* final_g      = (const float*)d_in[21];
    const float* final_b      = (const float*)d_in[22];
    const int*   edge_index   = (const int*)d_in[23];
    const int*   n_counts     = (const int*)d_in[24];
    const int*   root         = (const int*)d_in[25];
    int E = in_sizes[23] / 2;

    float *m_p,*r_p,*t_p,*deg_p,*out_p,*h_p,*q_p,*k_p,*v_p,*o_p,*x_p,*f1_p;
    int *cnt_p;
    cudaGetSymbolAddress((void**)&m_p,   g_m);
    cudaGetSymbolAddress((void**)&r_p,   g_r);
    cudaGetSymbolAddress((void**)&t_p,   g_t);
    cudaGetSymbolAddress((void**)&deg_p, g_deg);
    cudaGetSymbolAddress((void**)&out_p, g_out);
    cudaGetSymbolAddress((void**)&h_p,   g_h);
    cudaGetSymbolAddress((void**)&q_p,   g_q);
    cudaGetSymbolAddress((void**)&k_p,   g_k);
    cudaGetSymbolAddress((void**)&v_p,   g_v);
    cudaGetSymbolAddress((void**)&o_p,   g_o);
    cudaGetSymbolAddress((void**)&x_p,   g_x);
    cudaGetSymbolAddress((void**)&f1_p,  g_f1);
    cudaGetSymbolAddress((void**)&cnt_p, g_cnt);

    // ---- adjacency + MCL ----
    k_zero<<<(Bb*Nn*Nn+255)/256,256>>>(m_p, Bb*Nn*Nn);
    k_build_adj<<<(E+255)/256,256>>>(edge_index, E);
    k_selfloop<<<(BNn+255)/256,256>>>(n_counts);
    k_rownorm<<<Bb*Nn/4,256>>>(m_p, m_p, 0);
    const float* rcur = m_p;
    for(int i=0;i<6;i++){
        k_bmm<<<dim3(4,4,Bb),256>>>(m_p, rcur, t_p);
        k_rownorm<<<Bb*Nn/4,256>>>(t_p, r_p, ((i+1)%3==0)?1:0);
        rcur = r_p;
    }

    // ---- degree / edge norm ----
    k_zero<<<(BNn+255)/256,256>>>(deg_p, BNn);
    k_deg<<<(E+255)/256,256>>>(edge_index, E);
    k_enorm<<<(E+255)/256,256>>>(edge_index, E);

    // ---- CSR build (edges sorted by target) ----
    k_zeroi<<<(BNn+255)/256,256>>>(cnt_p, BNn);
    k_csr_count<<<(E+255)/256,256>>>(edge_index, E);
    k_csr_scan<<<1,1024>>>();
    k_csr_scatter<<<(E+255)/256,256>>>(edge_index, E);

    // ---- out = input ----
    cudaMemcpyAsync(out_p, input_x, (size_t)BNn*Ff*sizeof(float), cudaMemcpyDeviceToDevice, 0);

    dim3 g128(Ff/64, BNn/64);        // (2,64)
    dim3 g256(2*Ff/64, BNn/64);      // (4,64)
    dim3 gqkv(Ff/64, BNn/64, 3);     // (2,64,3)

    for(int l=0;l<Ll;l++){
        // ---- GCN ----
        k_gemm_tc<0><<<g128,128>>>(out_p, gcn_lin_w + (size_t)l*Ff*Ff, nullptr, h_p, Ff, Ff, 1.f);
        k_gcn<<<BNn/8,256>>>(edge_index, E, edge_attr, gcn_edge_w + (size_t)l*Ff*7,
                             gcn_norm_g + l*Ff, gcn_norm_b + l*Ff,
                             gcn_root_emb + (size_t)l*2*Ff, root);

        // ---- attention ----
        k_qkv_tc<<<gqkv,128>>>(out_p, q_w + (size_t)l*Ff*Ff, k_w + (size_t)l*Ff*Ff, v_w + (size_t)l*Ff*Ff);
        k_attn<<<dim3(Hh,Bb),256>>>(mcl_w + l*Hh, n_counts);
        k_gemm_tc<0><<<g128,128>>>(o_p, merge_w + (size_t)l*Ff*Ff, merge_b + l*Ff, h_p, Ff, Ff, 1.f);
        k_addln<<<BNn/8,256>>>(h_p, out_p, ln_in_g + l*Ff, ln_in_b + l*Ff, x_p);

        // ---- FFN ----
        k_gemm_tc<1><<<g256,128>>>(x_p, ffn_w1 + (size_t)l*2*Ff*Ff, ffn_b1 + (size_t)l*2*Ff,
                                   f1_p, 2*Ff, Ff, 1.f);
        k_gemm_tc<0><<<g128,128>>>(f1_p, ffn_w2 + (size_t)l*Ff*2*Ff, ffn_b2 + l*Ff,
                                   h_p, Ff, 2*Ff, 1.f);
        k_addln<<<BNn/8,256>>>(x_p, h_p, ln_ffn_g + l*Ff, ln_ffn_b + l*Ff, out_p);
    }

    // ---- final layernorm ----
    k_addln<<<BNn/8,256>>>(out_p, nullptr, final_g, final_b, (float*)d_out);
}